// round 17
// baseline (speedup 1.0000x reference)
#include <cuda_runtime.h>
#include <cstddef>

// Wave FDTD scan, register-resident, per-thread tag-based neighbor sync.
// y_t = w*(up+dn+lf+rg) + d*y_{t-1} + e*y_{t-2}, source at (96,32).
// One 8-CTA cluster per batch; CTA owns 24 rows x 192 cols; 192 threads,
// each owning a 2-col x 12-row register tile (packed f32x2).
// Inter-CTA: DSMEM halo push + release-store of a monotonic step tag;
// consumer spin-loads with acquire. No cluster.sync / mbarrier in the loop.

#define NXg 192
#define NYg 192
#define Tg  256
#define CLUSTER 8
#define ROWS_PER 24
#define ROWS_T 12
#define CPT 96
#define THREADS 192

typedef unsigned long long ull;

// ---- packed f32x2 math ----
__device__ __forceinline__ ull f2add(ull a, ull b) {
    ull r; asm("add.rn.f32x2 %0,%1,%2;" : "=l"(r) : "l"(a), "l"(b)); return r;
}
__device__ __forceinline__ ull f2mul(ull a, ull b) {
    ull r; asm("mul.rn.f32x2 %0,%1,%2;" : "=l"(r) : "l"(a), "l"(b)); return r;
}
__device__ __forceinline__ ull f2fma(ull a, ull b, ull c) {
    ull r; asm("fma.rn.f32x2 %0,%1,%2,%3;" : "=l"(r) : "l"(a), "l"(b), "l"(c)); return r;
}
__device__ __forceinline__ ull pack2(float lo, float hi) {
    ull r; asm("mov.b64 %0,{%1,%2};" : "=l"(r) : "f"(lo), "f"(hi)); return r;
}
__device__ __forceinline__ void unpack2(ull v, float& lo, float& hi) {
    asm("mov.b64 {%0,%1},%2;" : "=f"(lo), "=f"(hi) : "l"(v));
}

// ---- cluster helpers ----
__device__ __forceinline__ unsigned mapa_u32(unsigned addr, unsigned rank) {
    unsigned ret;
    asm volatile("mapa.shared::cluster.u32 %0, %1, %2;" : "=r"(ret) : "r"(addr), "r"(rank));
    return ret;
}
__device__ __forceinline__ void st_cluster_u64(unsigned addr, ull v) {
    asm volatile("st.shared::cluster.b64 [%0], %1;" :: "r"(addr), "l"(v) : "memory");
}
// Release store of the tag: orders the preceding data store, cluster scope.
__device__ __forceinline__ void st_cluster_rel_s32(unsigned addr, int v) {
    asm volatile("st.release.cluster.shared::cluster.b32 [%0], %1;"
                 :: "r"(addr), "r"(v) : "memory");
}
// Acquire load of the tag (local SMEM word written by a peer CTA).
__device__ __forceinline__ int ld_acq_s32(unsigned addr) {
    int v;
    asm volatile("ld.acquire.cluster.shared::cta.b32 %0, [%1];"
                 : "=r"(v) : "r"(addr) : "memory");
    return v;
}
__device__ __forceinline__ void cluster_sync_() {
    asm volatile("barrier.cluster.arrive.aligned;" ::: "memory");
    asm volatile("barrier.cluster.wait.aligned;"   ::: "memory");
}

__global__ void __launch_bounds__(THREADS, 1) __cluster_dims__(CLUSTER, 1, 1)
wave_scan_kernel(const float* __restrict__ xin,
                 const float* __restrict__ cin,
                 const float* __restrict__ bin,
                 float* __restrict__ out)
{
    __shared__ ull dsTop[2][CPT];           // halo row above strip (pushed by rk-1's hf1)
    __shared__ ull dsBot[2][CPT];           // halo row below strip (pushed by rk+1's hf0)
    __shared__ int tagTop[CPT];             // last step index delivered into dsTop
    __shared__ int tagBot[CPT];             // last step index delivered into dsBot
    __shared__ ull mid11[2][CPT];           // hf0 row 11 -> hf1's up neighbor
    __shared__ ull mid12[2][CPT];           // hf1 row 0  -> hf0's dn neighbor
    __shared__ float ebR[2][2][2][ROWS_T];  // warp right-edge cols
    __shared__ float ebL[2][2][3][ROWS_T];  // warp left-edge cols
    __shared__ float xs[Tg];

    const int tid   = threadIdx.x;
    const int lane  = tid & 31;
    const int cp    = tid % CPT;
    const int hf    = tid / CPT;            // 0: rows 0..11 of strip, 1: rows 12..23
    const int wInHf = cp >> 5;
    const int rk    = blockIdx.x;
    const int bt    = blockIdx.y;

    // Zero exchange buffers (global-boundary halos stay zero forever).
    if (tid < CPT) {
        dsTop[0][tid] = 0; dsTop[1][tid] = 0;
        dsBot[0][tid] = 0; dsBot[1][tid] = 0;
        mid11[0][tid] = 0; mid11[1][tid] = 0;
        mid12[0][tid] = 0; mid12[1][tid] = 0;
        tagTop[tid] = -1;  tagBot[tid] = -1;
    }
    for (int i = tid; i < 2*2*2*ROWS_T; i += THREADS) ((float*)ebR)[i] = 0.0f;
    for (int i = tid; i < 2*2*3*ROWS_T; i += THREADS) ((float*)ebL)[i] = 0.0f;
    for (int i = tid; i < Tg; i += THREADS) xs[i] = xin[bt * Tg + i];

    // Constants
    const float dtv     = 1e-3f;
    const float inv_dt2 = 1.0f / (dtv * dtv);
    const float Hv      = dtv * 1.4142135623730951f * 1.01f;
    const float inv_h2  = 1.0f / (Hv * Hv);

    const int r0 = rk * ROWS_PER + hf * ROWS_T;

    ull wv[ROWS_T], dv[ROWS_T], ev[ROWS_T], y1[ROWS_T], y2[ROWS_T];
#pragma unroll
    for (int r = 0; r < ROWS_T; r++) {
        const int gi = (r0 + r) * NYg + 2 * cp;
        const float2 c2 = *(const float2*)(cin + gi);
        const float2 b2 = *(const float2*)(bin + gi);
        float wq[2], dq[2], eq[2];
        {
            const float hb = 0.5f * b2.x / dtv;
            const float ai = 1.0f / (inv_dt2 + hb);
            wq[0] = ai * c2.x * c2.x * inv_h2;
            dq[0] = 2.0f * inv_dt2 * ai - 4.0f * wq[0];
            eq[0] = -(inv_dt2 - hb) * ai;
        }
        {
            const float hb = 0.5f * b2.y / dtv;
            const float ai = 1.0f / (inv_dt2 + hb);
            wq[1] = ai * c2.y * c2.y * inv_h2;
            dq[1] = 2.0f * inv_dt2 * ai - 4.0f * wq[1];
            eq[1] = -(inv_dt2 - hb) * ai;
        }
        wv[r] = pack2(wq[0], wq[1]);
        dv[r] = pack2(dq[0], dq[1]);
        ev[r] = pack2(eq[0], eq[1]);
        y1[r] = 0ull; y2[r] = 0ull;
    }

    const bool isSrc = (rk == 4) && (hf == 0) && (cp == 16);  // row 96, col 32
    float* oBase = out + ((size_t)bt * Tg) * (NXg * NYg) + (size_t)r0 * NYg + 2 * cp;

    // Push / wait setup.
    //  hf0 pushes strip row 0  up  -> (rk-1).dsBot + (rk-1).tagBot; waits on own tagTop.
    //  hf1 pushes strip row 23 down-> (rk+1).dsTop + (rk+1).tagTop; waits on own tagBot.
    const bool pushUp = (hf == 0) && (rk > 0);
    const bool pushDn = (hf == 1) && (rk < CLUSTER - 1);
    unsigned dA0 = 0, dA1 = 0, tA = 0;
    if (pushUp) {
        dA0 = mapa_u32((unsigned)__cvta_generic_to_shared(&dsBot[0][cp]), (unsigned)(rk - 1));
        dA1 = mapa_u32((unsigned)__cvta_generic_to_shared(&dsBot[1][cp]), (unsigned)(rk - 1));
        tA  = mapa_u32((unsigned)__cvta_generic_to_shared(&tagBot[cp]),   (unsigned)(rk - 1));
    }
    if (pushDn) {
        dA0 = mapa_u32((unsigned)__cvta_generic_to_shared(&dsTop[0][cp]), (unsigned)(rk + 1));
        dA1 = mapa_u32((unsigned)__cvta_generic_to_shared(&dsTop[1][cp]), (unsigned)(rk + 1));
        tA  = mapa_u32((unsigned)__cvta_generic_to_shared(&tagTop[cp]),   (unsigned)(rk + 1));
    }
    const unsigned myTagA = (unsigned)__cvta_generic_to_shared(
        (hf == 0) ? &tagTop[cp] : &tagBot[cp]);
    const bool doWait = (hf == 0) ? (rk > 0) : (rk < CLUSTER - 1);

#define ROWSTEP(r, up, dn, doSrc) do {                                          \
        const ull cen = y1[r];                                                  \
        float lo_, hi_; unpack2(cen, lo_, hi_);                                 \
        float lfs = __shfl_up_sync(0xffffffffu, hi_, 1);                        \
        float rgs = __shfl_down_sync(0xffffffffu, lo_, 1);                      \
        if (lane == 0)  lfs = (wInHf == 0) ? 0.0f : ebR[s][hf][wInHf - 1][r];   \
        if (lane == 31) rgs = (wInHf == 2) ? 0.0f : ebL[s][hf][wInHf + 1][r];   \
        const ull ssum = f2add(f2add((up), (dn)),                               \
                               f2add(pack2(lfs, lo_), pack2(hi_, rgs)));        \
        ull yn = f2fma(wv[r], ssum, f2fma(dv[r], cen, f2mul(ev[r], y2[r])));    \
        if (doSrc) yn = f2add(yn, srcAdd);                                      \
        y2[r] = cen; y1[r] = yn;                                                \
        *(ull*)(oT + (size_t)(r) * NYg) = yn;                                   \
    } while (0)

    cluster_sync_();   // zeros, tag inits, xs visible cluster-wide

    for (int t = 0; t < Tg; t++) {
        const int s = (t + 1) & 1;                 // read slot (y_{t-1} edges)
        const int w = t & 1;                       // write slot (y_t edges)
        const ull srcAdd = pack2(isSrc ? xs[t] : 0.0f, 0.0f);
        float* oT = oBase + (size_t)t * (NXg * NYg);

        if (hf == 0) {
            // Interior rows first (no remote dependency).
#pragma unroll
            for (int r = 1; r < ROWS_T; r++) {
                const ull up = (r == 1) ? y1[0] : y2[r - 1];   // old value of row above
                const ull dn = (r == ROWS_T - 1) ? mid12[s][cp] : y1[r + 1];
                ROWSTEP(r, up, dn, false);
            }
            if (t > 0 && doWait) { while (ld_acq_s32(myTagA) < t - 1) {} }
            ROWSTEP(0, dsTop[s][cp], y2[1], true);
            if (pushUp && t < Tg - 1) {
                st_cluster_u64(w ? dA1 : dA0, y1[0]);
                st_cluster_rel_s32(tA, t);
            }
        } else {
#pragma unroll
            for (int r = 0; r < ROWS_T - 1; r++) {
                const ull up = (r == 0) ? mid11[s][cp] : y2[r - 1];
                const ull dn = y1[r + 1];
                ROWSTEP(r, up, dn, false);
            }
            if (t > 0 && doWait) { while (ld_acq_s32(myTagA) < t - 1) {} }
            ROWSTEP(ROWS_T - 1, y2[ROWS_T - 2], dsBot[s][cp], false);
            if (pushDn && t < Tg - 1) {
                st_cluster_u64(w ? dA1 : dA0, y1[ROWS_T - 1]);
                st_cluster_rel_s32(tA, t);
            }
        }

        // Intra-CTA edge publications for step t+1 (slot w).
        if (lane == 31 && wInHf < 2) {
#pragma unroll
            for (int r = 0; r < ROWS_T; r++) {
                float lo, hi; unpack2(y1[r], lo, hi);
                ebR[w][hf][wInHf][r] = hi;
            }
        }
        if (lane == 0 && wInHf > 0) {
#pragma unroll
            for (int r = 0; r < ROWS_T; r++) {
                float lo, hi; unpack2(y1[r], lo, hi);
                ebL[w][hf][wInHf][r] = lo;
            }
        }
        if (hf == 0) mid11[w][cp] = y1[ROWS_T - 1];
        else         mid12[w][cp] = y1[0];

        __syncthreads();   // intra-CTA: publications visible for step t+1
    }
#undef ROWSTEP
}

extern "C" void kernel_launch(void* const* d_in, const int* in_sizes, int n_in,
                              void* d_out, int out_size) {
    const float* x = (const float*)d_in[0];   // [B, T, 1]
    const float* c = (const float*)d_in[1];   // [192, 192]
    const float* b = (const float*)d_in[2];   // [192, 192]
    float* out = (float*)d_out;               // [B, T, 192, 192]

    const int B = in_sizes[0] / Tg;           // 4
    dim3 grid(CLUSTER, B, 1);
    wave_scan_kernel<<<grid, THREADS>>>(x, c, b, out);
}